// round 2
// baseline (speedup 1.0000x reference)
#include <cuda_runtime.h>

#define T_STEPS 131072
#define FEATS   8
#define HIDDEN  256
#define BUF     50
#define MAX_K   10
#define BLK     256

// Scratch for the per-timestep fractal dimension (static device global; no allocs).
__device__ float g_hfd[T_STEPS];

// ---------------------------------------------------------------------------
// Kernel 1: Higuchi fractal dimension per timestep over trailing BUF window.
// ---------------------------------------------------------------------------
__global__ __launch_bounds__(BLK)
void hfd_kernel(const float* __restrict__ x)
{
    __shared__ float s_p[BLK + BUF - 1];   // prices covering [t0-49, t0+255]

    const int t0     = blockIdx.x * BLK;
    const int base_g = t0 - (BUF - 1);

    // Coalesced staging of the strided close-price column.
    for (int i = threadIdx.x; i < BLK + BUF - 1; i += BLK) {
        int g = base_g + i;
        s_p[i] = (g >= 0) ? x[g * FEATS + 3] : 0.0f;   // g <= t0+255 < T always
    }
    __syncthreads();

    const int t = t0 + threadIdx.x;
    float hfd = 0.0f;

    if (t >= BUF - 1) {
        // ---------- steady state: window length n = 50, fully unrolled ----------
        float a[BUF];
        #pragma unroll
        for (int i = 0; i < BUF; i++) a[i] = s_p[threadIdx.x + i];

        const float nm1f = (float)(BUF - 1);   // 49
        float c = 0.f, sx = 0.f, sy = 0.f, sxy = 0.f, sxx = 0.f;

        #pragma unroll
        for (int k = 1; k <= MAX_K; k++) {
            float acc = 0.0f;
            #pragma unroll
            for (int m = 0; m < k; m++) {
                const int len = (BUF - 1 - m) / k + 1;   // compile-time
                float s = 0.0f;
                #pragma unroll
                for (int q = m; q + k <= BUF - 1; q += k)
                    s += fabsf(a[q + k] - a[q]);
                if (len >= 2)
                    acc += s * nm1f / ((float)len * (float)k);
            }
            const float Lk = acc / (float)k;
            if (Lk > 0.0f) {
                const float yk = logf(Lk);
                const float xk = logf((float)k);
                c += 1.0f; sx += xk; sy += yk; sxy += yk * xk; sxx += xk * xk;
            }
        }
        const float denom = c * sxx - sx * sx;
        if (c > 1.0f && denom != 0.0f)
            hfd = -(c * sxy - sx * sy) / denom;
    }
    else if (t >= MAX_K) {
        // ---------- warmup region: n = t+1 in [11, 49], generic path ----------
        const int   nm1  = t;           // start = 0 here
        const float nm1f = (float)nm1;
        const int   base = -base_g;     // shared index of global price[0]

        float c = 0.f, sx = 0.f, sy = 0.f, sxy = 0.f, sxx = 0.f;
        for (int k = 1; k <= MAX_K; k++) {
            float acc = 0.0f;
            for (int m = 0; m < k; m++) {
                const int len = (nm1 >= m) ? (nm1 - m) / k + 1 : 0;
                float s = 0.0f;
                for (int q = m; q + k <= nm1; q += k)
                    s += fabsf(s_p[base + q + k] - s_p[base + q]);
                if (len >= 2)
                    acc += s * nm1f / ((float)len * (float)k);
            }
            const float Lk = acc / (float)k;
            if (Lk > 0.0f) {
                const float yk = logf(Lk);
                const float xk = logf((float)k);
                c += 1.0f; sx += xk; sy += yk; sxy += yk * xk; sxx += xk * xk;
            }
        }
        const float denom = c * sxx - sx * sx;
        if (c > 1.0f && denom != 0.0f)
            hfd = -(c * sxy - sx * sy) / denom;
    }
    // t < MAX_K: n < 11 -> masked to 0.

    g_hfd[t] = hfd;
}

// ---------------------------------------------------------------------------
// Kernel 2: out[t, j] = relu(hfd[t] * w[j] + b[j]), float4 stores.
// 4 rows per 256-thread block; 64 threads (16 float4s... 64 float4s) per row.
// ---------------------------------------------------------------------------
__global__ __launch_bounds__(256)
void out_kernel(const float* __restrict__ w,
                const float* __restrict__ b,
                float4* __restrict__ out)
{
    const int t = blockIdx.x * 4 + (threadIdx.x >> 6);
    const int j = threadIdx.x & 63;                 // float4 column index

    const float  h  = g_hfd[t];                     // warp-uniform broadcast
    const float4 w4 = __ldg(((const float4*)w) + j);
    const float4 b4 = __ldg(((const float4*)b) + j);

    float4 o;
    o.x = fmaxf(fmaf(h, w4.x, b4.x), 0.0f);
    o.y = fmaxf(fmaf(h, w4.y, b4.y), 0.0f);
    o.z = fmaxf(fmaf(h, w4.z, b4.z), 0.0f);
    o.w = fmaxf(fmaf(h, w4.w, b4.w), 0.0f);

    out[t * (HIDDEN / 4) + j] = o;
}

// ---------------------------------------------------------------------------
extern "C" void kernel_launch(void* const* d_in, const int* in_sizes, int n_in,
                              void* d_out, int out_size)
{
    const float* x = (const float*)d_in[0];   // [T, 8]
    const float* w = (const float*)d_in[1];   // [256, 1] -> flat [256]
    const float* b = (const float*)d_in[2];   // [256]
    float4* out = (float4*)d_out;             // [T, 256] f32

    hfd_kernel<<<T_STEPS / BLK, BLK>>>(x);
    out_kernel<<<T_STEPS / 4, 256>>>(w, b, out);
}

// round 3
// speedup vs baseline: 1.2351x; 1.2351x over previous
#include <cuda_runtime.h>

#define T_STEPS 131072
#define FEATS   8
#define HIDDEN  256
#define BUF     50
#define MAX_K   10
#define BLK     256

// ---------------------------------------------------------------------------
// Fused kernel: per-block
//   Phase A: stage 305 prices -> shared; each thread computes HFD for its
//            timestep (fully unrolled, compile-time weights) -> s_h[256]
//   Phase B: stream the 256x256 f32 output tile with float4 streaming stores.
// ---------------------------------------------------------------------------
__global__ __launch_bounds__(BLK)
void fused_hfd_kernel(const float* __restrict__ x,
                      const float* __restrict__ w,
                      const float* __restrict__ b,
                      float4* __restrict__ out)
{
    __shared__ float s_p[BLK + BUF - 1];   // prices covering [t0-49, t0+255]
    __shared__ float s_h[BLK];             // per-timestep HFD

    const int t0     = blockIdx.x * BLK;
    const int base_g = t0 - (BUF - 1);

    // Coalesced staging of the strided close-price column (stride 8 floats).
    for (int i = threadIdx.x; i < BLK + BUF - 1; i += BLK) {
        const int g = base_g + i;
        s_p[i] = (g >= 0) ? x[g * FEATS + 3] : 0.0f;   // g <= t0+255 < T always
    }
    __syncthreads();

    // ---------------- Phase A: HFD ----------------
    float hfd = 0.0f;

    if (blockIdx.x > 0 || threadIdx.x >= BUF - 1) {
        // Steady state: window length n = 50. Fully unrolled, branch-free.
        float a[BUF];
        #pragma unroll
        for (int i = 0; i < BUF; i++) a[i] = s_p[threadIdx.x + i];

        float c = 0.f, sx = 0.f, sy = 0.f, sxy = 0.f, sxx = 0.f;

        #pragma unroll
        for (int k = 1; k <= MAX_K; k++) {
            // Lk = sum_q  49/(len(q%k) * k^2) * |a[q+k]-a[q]| ,  q in [0, 49-k]
            // (len >= 5 for all k<=10, so the len>=2 guard is compile-time true)
            float acc = 0.0f;
            #pragma unroll
            for (int q = 0; q + k <= BUF - 1; q++) {
                const int   m   = q % k;                       // compile-time
                const int   len = (BUF - 1 - m) / k + 1;       // compile-time
                const float wgt = 49.0f / ((float)len * (float)k * (float)k);
                acc = fmaf(wgt, fabsf(a[q + k] - a[q]), acc);
            }
            if (acc > 0.0f) {
                const float yk = logf(acc);
                const float xk = logf((float)k);               // compile-time
                c += 1.0f; sx += xk; sy += yk; sxy += yk * xk; sxx += xk * xk;
            }
        }
        const float denom = c * sxx - sx * sx;
        if (c > 1.0f && denom != 0.0f)
            hfd = -(c * sxy - sx * sy) / denom;
    }
    else if (threadIdx.x >= MAX_K) {
        // Warmup (block 0, threads 10..48): n = t+1 in [11,49], generic path.
        const int   t    = threadIdx.x;
        const int   nm1  = t;
        const float nm1f = (float)nm1;
        const int   base = BUF - 1;            // s_p index of global price[0]

        float c = 0.f, sx = 0.f, sy = 0.f, sxy = 0.f, sxx = 0.f;
        for (int k = 1; k <= MAX_K; k++) {
            float acc = 0.0f;
            for (int m = 0; m < k; m++) {
                const int len = (nm1 - m) / k + 1;
                float s = 0.0f;
                for (int q = m; q + k <= nm1; q += k)
                    s += fabsf(s_p[base + q + k] - s_p[base + q]);
                if (len >= 2)
                    acc += s * nm1f / ((float)len * (float)k);
            }
            const float Lk = acc / (float)k;
            if (Lk > 0.0f) {
                const float yk = logf(Lk);
                const float xk = logf((float)k);
                c += 1.0f; sx += xk; sy += yk; sxy += yk * xk; sxx += xk * xk;
            }
        }
        const float denom = c * sxx - sx * sx;
        if (c > 1.0f && denom != 0.0f)
            hfd = -(c * sxy - sx * sy) / denom;
    }
    // else: n < 11 -> hfd stays 0.

    s_h[threadIdx.x] = hfd;
    __syncthreads();

    // ---------------- Phase B: stream output tile ----------------
    // 256 threads = 4 row-lanes x 64 float4-columns. Each thread writes 64
    // float4s (one per row in its lane). Warp stores are 512B contiguous.
    const int j  = threadIdx.x & 63;        // float4 column
    const int r0 = threadIdx.x >> 6;        // row lane 0..3

    const float4 w4 = __ldg(((const float4*)w) + j);
    const float4 b4 = __ldg(((const float4*)b) + j);

    float4* const obase = out + (size_t)t0 * (HIDDEN / 4) + j;

    #pragma unroll 8
    for (int rr = 0; rr < BLK / 4; rr++) {
        const int   row = (rr << 2) | r0;
        const float h   = s_h[row];
        float4 o;
        o.x = fmaxf(fmaf(h, w4.x, b4.x), 0.0f);
        o.y = fmaxf(fmaf(h, w4.y, b4.y), 0.0f);
        o.z = fmaxf(fmaf(h, w4.z, b4.z), 0.0f);
        o.w = fmaxf(fmaf(h, w4.w, b4.w), 0.0f);
        __stcs(obase + (size_t)row * (HIDDEN / 4), o);
    }
}

// ---------------------------------------------------------------------------
extern "C" void kernel_launch(void* const* d_in, const int* in_sizes, int n_in,
                              void* d_out, int out_size)
{
    const float* x = (const float*)d_in[0];   // [T, 8]
    const float* w = (const float*)d_in[1];   // [256, 1] -> flat [256]
    const float* b = (const float*)d_in[2];   // [256]
    float4* out = (float4*)d_out;             // [T, 256] f32

    fused_hfd_kernel<<<T_STEPS / BLK, BLK>>>(x, w, b, out);
}

// round 4
// speedup vs baseline: 1.3920x; 1.1270x over previous
#include <cuda_runtime.h>

#define T_STEPS 131072
#define FEATS   8
#define HIDDEN  256
#define BUF     50
#define MAX_K   10
#define BLK     256
#define ROWS    128                    // timesteps per block
#define SP_N    (ROWS + BUF - 1)       // 177 staged prices

// Compile-time natural logs of k (folds to immediates for literal k).
__device__ __forceinline__ float kconst_log(int k) {
    constexpr float LOGK[11] = {0.f, 0.f, 0.69314718f, 1.09861229f, 1.38629436f,
                                1.60943791f, 1.79175947f, 1.94591015f,
                                2.07944154f, 2.19722458f, 2.30258509f};
    return LOGK[k];
}

// Partial regression sums over k = {1+HALF, 3+HALF, ..., 9+HALF}.
// acc_k already equals Lk (the /k and /len scalings are folded into wgt).
template<int HALF>
__device__ __forceinline__ void steady_partial(const float* __restrict__ a,
        float& c, float& sx, float& sy, float& sxy, float& sxx)
{
    #pragma unroll
    for (int kk = 0; kk < 5; kk++) {
        const int k = 2 * kk + 1 + HALF;
        float acc = 0.0f;
        #pragma unroll
        for (int q = 0; q + k <= BUF - 1; q++) {
            const int   m   = q % k;                   // compile-time
            const int   len = (BUF - 1 - m) / k + 1;   // compile-time, >= 4
            const float wgt = 49.0f / ((float)len * (float)(k * k));
            acc = fmaf(wgt, fabsf(a[q + k] - a[q]), acc);
        }
        if (acc > 0.0f) {
            const float yk = __logf(acc);
            const float xk = kconst_log(k);
            c += 1.0f; sx += xk; sy += yk; sxy += yk * xk; sxx += xk * xk;
        }
    }
}

__global__ __launch_bounds__(BLK)
void fused_hfd_kernel(const float* __restrict__ x,
                      const float* __restrict__ w,
                      const float* __restrict__ b,
                      float4* __restrict__ out)
{
    __shared__ float s_p[SP_N];            // prices [t0-49, t0+127]
    __shared__ float s_h[ROWS];            // per-row HFD
    __shared__ float s_part[5][ROWS];      // half-1 partial sums

    const int t0     = blockIdx.x * ROWS;
    const int base_g = t0 - (BUF - 1);

    // Coalesced staging of close-price column (stride 8 floats).
    for (int i = threadIdx.x; i < SP_N; i += BLK) {
        const int g = base_g + i;
        s_p[i] = (g >= 0) ? x[g * FEATS + 3] : 0.0f;
    }
    __syncthreads();

    // ---------------- Phase A: HFD, pair-split across warp pairs ----------
    // Warps (2i, 2i+1) both own rows [32i, 32i+32); warp parity picks k-set.
    const int wid  = threadIdx.x >> 5;
    const int lane = threadIdx.x & 31;
    const int half = wid & 1;                    // warp-uniform
    const int ts   = ((wid >> 1) << 5) | lane;   // local row 0..127

    float a[BUF];
    #pragma unroll
    for (int i = 0; i < BUF; i++) a[i] = s_p[ts + i];

    float c = 0.f, sx = 0.f, sy = 0.f, sxy = 0.f, sxx = 0.f;
    if (half) steady_partial<1>(a, c, sx, sy, sxy, sxx);
    else      steady_partial<0>(a, c, sx, sy, sxy, sxx);

    if (half) {
        s_part[0][ts] = c;   s_part[1][ts] = sx;  s_part[2][ts] = sy;
        s_part[3][ts] = sxy; s_part[4][ts] = sxx;
    }
    __syncthreads();

    if (!half) {
        c   += s_part[0][ts]; sx  += s_part[1][ts]; sy += s_part[2][ts];
        sxy += s_part[3][ts]; sxx += s_part[4][ts];

        float hfd = 0.0f;
        const float denom = c * sxx - sx * sx;
        if (c > 1.0f && denom != 0.0f)
            hfd = -(c * sxy - sx * sy) / denom;

        // Block 0 warmup region: n = ts+1 < 50 -> generic path / zero.
        if (blockIdx.x == 0 && ts <= BUF - 2) {
            hfd = 0.0f;
            if (ts >= MAX_K) {
                const int   nm1  = ts;
                const float nm1f = (float)nm1;
                const int   base = BUF - 1;     // s_p index of global price[0]
                float c2=0.f, sx2=0.f, sy2=0.f, sxy2=0.f, sxx2=0.f;
                for (int k = 1; k <= MAX_K; k++) {
                    float acc = 0.0f;
                    for (int m = 0; m < k; m++) {
                        const int len = (nm1 - m) / k + 1;
                        float s = 0.0f;
                        for (int q = m; q + k <= nm1; q += k)
                            s += fabsf(s_p[base + q + k] - s_p[base + q]);
                        if (len >= 2)
                            acc += s * nm1f / ((float)len * (float)k);
                    }
                    const float Lk = acc / (float)k;
                    if (Lk > 0.0f) {
                        const float yk = __logf(Lk);
                        const float xk = __logf((float)k);
                        c2 += 1.f; sx2 += xk; sy2 += yk;
                        sxy2 += yk * xk; sxx2 += xk * xk;
                    }
                }
                const float dn = c2 * sxx2 - sx2 * sx2;
                if (c2 > 1.0f && dn != 0.0f)
                    hfd = -(c2 * sxy2 - sx2 * sy2) / dn;
            }
        }
        s_h[ts] = hfd;
    }
    __syncthreads();

    // ---------------- Phase B: stream the 128x256 output tile --------------
    // 256 threads = 4 row-lanes x 64 float4-cols; 32 float4 stores/thread.
    const int j  = threadIdx.x & 63;
    const int r0 = threadIdx.x >> 6;

    const float4 w4 = __ldg(((const float4*)w) + j);
    const float4 b4 = __ldg(((const float4*)b) + j);

    float4* const obase = out + (size_t)t0 * (HIDDEN / 4) + j;

    #pragma unroll 8
    for (int rr = 0; rr < ROWS / 4; rr++) {
        const int   row = (rr << 2) | r0;
        const float h   = s_h[row];
        float4 o;
        o.x = fmaxf(fmaf(h, w4.x, b4.x), 0.0f);
        o.y = fmaxf(fmaf(h, w4.y, b4.y), 0.0f);
        o.z = fmaxf(fmaf(h, w4.z, b4.z), 0.0f);
        o.w = fmaxf(fmaf(h, w4.w, b4.w), 0.0f);
        __stcs(obase + (size_t)row * (HIDDEN / 4), o);
    }
}

// ---------------------------------------------------------------------------
extern "C" void kernel_launch(void* const* d_in, const int* in_sizes, int n_in,
                              void* d_out, int out_size)
{
    const float* x = (const float*)d_in[0];   // [T, 8]
    const float* w = (const float*)d_in[1];   // [256, 1] -> flat [256]
    const float* b = (const float*)d_in[2];   // [256]
    float4* out = (float4*)d_out;             // [T, 256] f32

    fused_hfd_kernel<<<T_STEPS / ROWS, BLK>>>(x, w, b, out);
}

// round 5
// speedup vs baseline: 1.4509x; 1.0422x over previous
#include <cuda_runtime.h>

#define T_STEPS 131072
#define FEATS   8
#define HIDDEN  256
#define BUF     50
#define MAX_K   10
#define BLK     256
#define ROWS    128                    // timesteps per block
#define SP_N    (ROWS + BUF - 1)       // 177 staged prices

// Offset of the d_k slab in s_d: sum_{j=1}^{k-1} (SP_N - j)
#define DOFF(k) (((k) - 1) * SP_N - (((k) - 1) * (k)) / 2)
#define D_TOTAL (MAX_K * SP_N - (MAX_K * (MAX_K + 1)) / 2)   // 1715

__device__ __forceinline__ float kconst_log(int k) {
    constexpr float LOGK[11] = {0.f, 0.f, 0.69314718f, 1.09861229f, 1.38629436f,
                                1.60943791f, 1.79175947f, 1.94591015f,
                                2.07944154f, 2.19722458f, 2.30258509f};
    return LOGK[k];
}

// Partial regression sums over k = {1+HALF, 3+HALF, ..., 9+HALF}.
// acc_k equals Lk directly (per-position scalings folded into compile-time wgt).
template<int HALF>
__device__ __forceinline__ void steady_partial(const float* __restrict__ s_d,
        const int ts, float& c, float& sx, float& sy, float& sxy, float& sxx)
{
    #pragma unroll
    for (int kk = 0; kk < 5; kk++) {
        const int k = 2 * kk + 1 + HALF;
        const float* __restrict__ dk = s_d + DOFF(k) + ts;
        float acc = 0.0f;
        #pragma unroll
        for (int q = 0; q + k <= BUF - 1; q++) {
            const int   m   = q % k;                   // compile-time
            const int   len = (BUF - 1 - m) / k + 1;   // compile-time, >= 4
            const float wgt = 49.0f / ((float)len * (float)(k * k));
            acc = fmaf(wgt, dk[q], acc);
        }
        if (acc > 0.0f) {
            const float yk = __logf(acc);
            const float xk = kconst_log(k);
            c += 1.0f; sx += xk; sy += yk; sxy += yk * xk; sxx += xk * xk;
        }
    }
}

__global__ __launch_bounds__(BLK, 8)
void fused_hfd_kernel(const float* __restrict__ x,
                      const float* __restrict__ w,
                      const float* __restrict__ b,
                      float4* __restrict__ out)
{
    __shared__ float s_p[SP_N];            // prices [t0-49, t0+127]
    __shared__ float s_d[D_TOTAL];         // shared lag-diffs, all k
    __shared__ float s_h[ROWS];            // per-row HFD
    __shared__ float s_part[5][ROWS];      // half-1 partial sums

    const int t0     = blockIdx.x * ROWS;
    const int base_g = t0 - (BUF - 1);

    // Coalesced staging of close-price column (stride 8 floats).
    for (int i = threadIdx.x; i < SP_N; i += BLK) {
        const int g = base_g + i;
        s_p[i] = (g >= 0) ? x[g * FEATS + 3] : 0.0f;
    }
    __syncthreads();

    // Cooperative lag-diff tables: d_k[i] = |p[i+k]-p[i]|, computed ONCE per block.
    #pragma unroll
    for (int k = 1; k <= MAX_K; k++) {
        const int n = SP_N - k;            // <= 176 < BLK -> one predicated pass
        const int i = threadIdx.x;
        if (i < n) s_d[DOFF(k) + i] = fabsf(s_p[i + k] - s_p[i]);
    }
    __syncthreads();

    // ---------------- Phase A: HFD, k-set split across warp pairs ----------
    const int wid  = threadIdx.x >> 5;
    const int lane = threadIdx.x & 31;
    const int half = wid & 1;                    // warp-uniform
    const int ts   = ((wid >> 1) << 5) | lane;   // local row 0..127

    float c = 0.f, sx = 0.f, sy = 0.f, sxy = 0.f, sxx = 0.f;
    if (half) steady_partial<1>(s_d, ts, c, sx, sy, sxy, sxx);
    else      steady_partial<0>(s_d, ts, c, sx, sy, sxy, sxx);

    if (half) {
        s_part[0][ts] = c;   s_part[1][ts] = sx;  s_part[2][ts] = sy;
        s_part[3][ts] = sxy; s_part[4][ts] = sxx;
    }
    __syncthreads();

    if (!half) {
        c   += s_part[0][ts]; sx  += s_part[1][ts]; sy += s_part[2][ts];
        sxy += s_part[3][ts]; sxx += s_part[4][ts];

        float hfd = 0.0f;
        const float denom = c * sxx - sx * sx;
        if (c > 1.0f && denom != 0.0f)
            hfd = -(c * sxy - sx * sy) / denom;

        // Block 0 warmup region: n = ts+1 < 50 -> generic path / zero.
        if (blockIdx.x == 0 && ts <= BUF - 2) {
            hfd = 0.0f;
            if (ts >= MAX_K) {
                const int   nm1  = ts;
                const float nm1f = (float)nm1;
                const int   base = BUF - 1;     // s_p index of global price[0]
                float c2=0.f, sx2=0.f, sy2=0.f, sxy2=0.f, sxx2=0.f;
                for (int k = 1; k <= MAX_K; k++) {
                    float acc = 0.0f;
                    for (int m = 0; m < k; m++) {
                        const int len = (nm1 - m) / k + 1;
                        float s = 0.0f;
                        for (int q = m; q + k <= nm1; q += k)
                            s += fabsf(s_p[base + q + k] - s_p[base + q]);
                        if (len >= 2)
                            acc += s * nm1f / ((float)len * (float)k);
                    }
                    const float Lk = acc / (float)k;
                    if (Lk > 0.0f) {
                        const float yk = __logf(Lk);
                        const float xk = __logf((float)k);
                        c2 += 1.f; sx2 += xk; sy2 += yk;
                        sxy2 += yk * xk; sxx2 += xk * xk;
                    }
                }
                const float dn = c2 * sxx2 - sx2 * sx2;
                if (c2 > 1.0f && dn != 0.0f)
                    hfd = -(c2 * sxy2 - sx2 * sy2) / dn;
            }
        }
        s_h[ts] = hfd;
    }
    __syncthreads();

    // ---------------- Phase B: stream the 128x256 output tile --------------
    // 256 threads = 4 row-lanes x 64 float4-cols; 32 float4 stores/thread.
    const int j  = threadIdx.x & 63;
    const int r0 = threadIdx.x >> 6;

    const float4 w4 = __ldg(((const float4*)w) + j);
    const float4 b4 = __ldg(((const float4*)b) + j);

    float4* const obase = out + (size_t)t0 * (HIDDEN / 4) + j;

    #pragma unroll 8
    for (int rr = 0; rr < ROWS / 4; rr++) {
        const int   row = (rr << 2) | r0;
        const float h   = s_h[row];
        float4 o;
        o.x = fmaxf(fmaf(h, w4.x, b4.x), 0.0f);
        o.y = fmaxf(fmaf(h, w4.y, b4.y), 0.0f);
        o.z = fmaxf(fmaf(h, w4.z, b4.z), 0.0f);
        o.w = fmaxf(fmaf(h, w4.w, b4.w), 0.0f);
        __stcs(obase + (size_t)row * (HIDDEN / 4), o);
    }
}

// ---------------------------------------------------------------------------
extern "C" void kernel_launch(void* const* d_in, const int* in_sizes, int n_in,
                              void* d_out, int out_size)
{
    const float* x = (const float*)d_in[0];   // [T, 8]
    const float* w = (const float*)d_in[1];   // [256, 1] -> flat [256]
    const float* b = (const float*)d_in[2];   // [256]
    float4* out = (float4*)d_out;             // [T, 256] f32

    fused_hfd_kernel<<<T_STEPS / ROWS, BLK>>>(x, w, b, out);
}